// round 15
// baseline (speedup 1.0000x reference)
#include <cuda_runtime.h>
#include <cstdint>

#define D   128   // LATDIM
#define AA  64    // ANCHOR_SET_NUM
#define MT  32    // n rows per main tile -> grid 313
#define CT  32    // t rows per k_pre2 C tile -> 20 C blocks + 1 V block
#define SDS 40    // sd/se stride (words); 40 % 32 == 8 -> conflict-free frags
#define SVS 136   // sv/sw stride (words); 136 % 32 == 8
#define SES 72    // V-block A stride (72 % 32 == 8)
#define SAS 132   // acc stride (words)
#define SCH 129   // chunk-sum stride (129 % 32 == 1 -> 2-way read conflicts max)

// __device__ scratch (allocation-free rule)
__device__ uint32_t g_Vt32[AA * D]; // V as tf32 bits [a][o]
__device__ float    g_C[10048 * D]; // [t][o]

// ---------------------------------------------------------------------------
// tf32 helpers (sm_80+ -> valid under compute_103)
// ---------------------------------------------------------------------------
__device__ __forceinline__ uint32_t f2tf32(float f) {
    uint32_t r;
    asm("cvt.rna.tf32.f32 %0, %1;" : "=r"(r) : "f"(f));
    return r;
}
__device__ __forceinline__ void mma_tf32(float& c0, float& c1, float& c2, float& c3,
                                         uint32_t a0, uint32_t a1, uint32_t a2,
                                         uint32_t a3, uint32_t b0, uint32_t b1) {
    asm("mma.sync.aligned.m16n8k8.row.col.f32.tf32.tf32.f32 "
        "{%0,%1,%2,%3}, {%4,%5,%6,%7}, {%8,%9}, {%0,%1,%2,%3};"
        : "+f"(c0), "+f"(c1), "+f"(c2), "+f"(c3)
        : "r"(a0), "r"(a1), "r"(a2), "r"(a3), "r"(b0), "r"(b1));
}

// smem word offsets for k_pre2
#define OFF_SW  0
#define OFF_SE  (OFF_SW + D * SVS)          // 17408
#define OFF_SCH (OFF_SE + D * SES)          // 17408 + 9216 = 26624
#define OFF_SA  (OFF_SCH + 70 * SCH + 2)    // 26624 + 9032 = 35656 (16B aligned)
#define PRE2_WORDS (OFF_SA + CT * SAS)      // 35656 + 4224 = 39880

// ---------------------------------------------------------------------------
// k_pre2: tensor-core precompute. grid = nCB + 1, 512 threads.
//  blocks [0, nCB): C[t][o] = sum_k E2[t][k] * (W2[o][k]/64) + b[o], 32 t/block
//  block nCB:       Vt32[a][o] = tf32( sum_k emb[anchor[a]][k] * (W1[o][k]/64) )
// Fragment layouts identical to the R9-proven k_main (strides ≡ 8 mod 32).
// ---------------------------------------------------------------------------
__global__ __launch_bounds__(512)
void k_pre2(const float* __restrict__ embeds,
            const float* __restrict__ W,
            const float* __restrict__ b,
            const int*   __restrict__ anchor,
            int N, int T, int nCB) {
    extern __shared__ __align__(16) uint32_t sm[];
    uint32_t* sw  = sm + OFF_SW;            // [128 k][SVS] B tile (tf32 bits)
    uint32_t* se  = sm + OFF_SE;            // A tile (tf32 bits)
    float*    sch = (float*)(sm + OFF_SCH); // [70][SCH] half-chunk sums
    float*    sa  = (float*)(sm + OFF_SA);  // [CT][SAS] accumulators

    const int tid = threadIdx.x;
    const int w   = tid >> 5;
    const int l   = tid & 31;
    const bool isV = ((int)blockIdx.x >= nCB);
    const int woff = isV ? 0 : D;
    const float sc = 1.0f / 64.0f;          // exact power of 2

    // ---- stage B = W-half^T, scaled, tf32 (both block types) ----
    // task i = (o, kq): lanes vary o -> STS conflict-free (bank = 8k+o)
    #pragma unroll
    for (int i = tid; i < D * 32; i += 512) {
        const int o  = i & 127;
        const int kq = (i >> 7) * 4;
        const float4 wv = __ldg((const float4*)&W[(size_t)o * (2 * D) + woff + kq]);
        sw[(kq + 0) * SVS + o] = f2tf32(wv.x * sc);
        sw[(kq + 1) * SVS + o] = f2tf32(wv.y * sc);
        sw[(kq + 2) * SVS + o] = f2tf32(wv.z * sc);
        sw[(kq + 3) * SVS + o] = f2tf32(wv.w * sc);
    }

    if (!isV) {
        // ================== C tile (32 windows) ==================
        const int t0 = blockIdx.x * CT;
        const int R  = min(CT, T - t0);

        // ---- half-chunk sums: task = (chunk, half), chunk = (t0+ch) mod T ----
        for (int task = w; task < 70; task += 16) {
            int tIdx = t0 + (task >> 1);
            if (tIdx >= T) tIdx -= T;
            const int rbase = 16 * tIdx + 8 * (task & 1);   // rbase+7 <= N-1
            float4 acc = {0.f, 0.f, 0.f, 0.f};
            #pragma unroll
            for (int i = 0; i < 8; i++) {
                const float4 v = __ldg((const float4*)
                    &embeds[(size_t)(rbase + i) * D + 4 * l]);
                acc.x += v.x; acc.y += v.y; acc.z += v.z; acc.w += v.w;
            }
            float* p = &sch[task * SCH + 4 * l];
            p[0] = acc.x; p[1] = acc.y; p[2] = acc.z; p[3] = acc.w;
        }
        __syncthreads();

        // ---- build A tile: se[k*SDS + r] = tf32(E2[t0+r][k]) ----
        // thread: r = tid&31 (lane-varying -> conflict-free STS), k = 8*(tid>>5)+i
        {
            const int r  = tid & 31;
            const int kg = tid >> 5;
            #pragma unroll
            for (int i = 0; i < 8; i++) {
                const int k = kg * 8 + i;
                float v = 0.f;
                #pragma unroll
                for (int c = 0; c < 4; c++)
                    v += sch[((r + c) * 2 + 0) * SCH + k]
                       + sch[((r + c) * 2 + 1) * SCH + k];
                se[k * SDS + r] = f2tf32(v);
            }
        }
        __syncthreads();

        // ---- MMA: warp (mw 0..1 -> 16 rows, oq 0..7 -> 16 cols); K=128 ----
        const int tig = l & 3;
        const int g   = l >> 2;
        const int mw  = w & 1;
        const int oq  = w >> 1;
        const int rowbase = 16 * mw;
        const int obase   = 16 * oq;

        float c[2][4];
        #pragma unroll
        for (int j = 0; j < 2; j++)
            #pragma unroll
            for (int q = 0; q < 4; q++) c[j][q] = 0.f;

        #pragma unroll
        for (int ks = 0; ks < 16; ks++) {
            const int k0 = 8 * ks + tig;
            const uint32_t a0 = se[k0 * SDS + rowbase + g];
            const uint32_t a1 = se[k0 * SDS + rowbase + g + 8];
            const uint32_t a2 = se[(k0 + 4) * SDS + rowbase + g];
            const uint32_t a3 = se[(k0 + 4) * SDS + rowbase + g + 8];
            #pragma unroll
            for (int j = 0; j < 2; j++) {
                const uint32_t b0 = sw[k0 * SVS + obase + 8 * j + g];
                const uint32_t b1 = sw[(k0 + 4) * SVS + obase + 8 * j + g];
                mma_tf32(c[j][0], c[j][1], c[j][2], c[j][3],
                         a0, a1, a2, a3, b0, b1);
            }
        }
        __syncthreads();

        // ---- accumulators -> padded smem ----
        #pragma unroll
        for (int j = 0; j < 2; j++) {
            const int col = obase + 8 * j + 2 * tig;
            float2 lo; lo.x = c[j][0]; lo.y = c[j][1];
            float2 hi; hi.x = c[j][2]; hi.y = c[j][3];
            *(float2*)&sa[(rowbase + g)     * SAS + col] = lo;
            *(float2*)&sa[(rowbase + g + 8) * SAS + col] = hi;
        }
        __syncthreads();

        // ---- coalesced store with bias: warp w -> rows 2w, 2w+1 ----
        const float4 bv = __ldg((const float4*)&b[4 * l]);
        #pragma unroll
        for (int r = 0; r < 2; r++) {
            const int row = 2 * w + r;
            if (row < R) {
                const float4 av = *(const float4*)&sa[row * SAS + 4 * l];
                float4 o;
                o.x = av.x + bv.x; o.y = av.y + bv.y;
                o.z = av.z + bv.z; o.w = av.w + bv.w;
                *(float4*)&g_C[(size_t)(t0 + row) * D + 4 * l] = o;
            }
        }
    } else {
        // ================== V tile (64 anchors) ==================
        // A: se[k*SES + r] = tf32(embeds[anchor[r]][k]); lanes vary r
        {
            const int r    = tid & 63;
            const int arow = __ldg(&anchor[r]);
            #pragma unroll
            for (int m = 0; m < 16; m++) {
                const int k = (tid >> 6) + 8 * m;
                se[k * SES + r] = f2tf32(__ldg(&embeds[(size_t)arow * D + k]));
            }
        }
        __syncthreads();

        // MMA: warp (mw 0..3 -> 16 rows, oq 0..3 -> 32 cols); K=128
        const int tig = l & 3;
        const int g   = l >> 2;
        const int mw  = w & 3;
        const int oq  = w >> 2;
        const int rowbase = 16 * mw;
        const int obase   = 32 * oq;

        float c[4][4];
        #pragma unroll
        for (int j = 0; j < 4; j++)
            #pragma unroll
            for (int q = 0; q < 4; q++) c[j][q] = 0.f;

        #pragma unroll
        for (int ks = 0; ks < 16; ks++) {
            const int k0 = 8 * ks + tig;
            const uint32_t a0 = se[k0 * SES + rowbase + g];
            const uint32_t a1 = se[k0 * SES + rowbase + g + 8];
            const uint32_t a2 = se[(k0 + 4) * SES + rowbase + g];
            const uint32_t a3 = se[(k0 + 4) * SES + rowbase + g + 8];
            #pragma unroll
            for (int j = 0; j < 4; j++) {
                const uint32_t b0 = sw[k0 * SVS + obase + 8 * j + g];
                const uint32_t b1 = sw[(k0 + 4) * SVS + obase + 8 * j + g];
                mma_tf32(c[j][0], c[j][1], c[j][2], c[j][3],
                         a0, a1, a2, a3, b0, b1);
            }
        }

        // direct scattered store of tf32 bits (tiny: one block)
        #pragma unroll
        for (int j = 0; j < 4; j++) {
            const int col = obase + 8 * j + 2 * tig;
            const int row = rowbase + g;
            uint2 lo; lo.x = f2tf32(c[j][0]); lo.y = f2tf32(c[j][1]);
            uint2 hi; hi.x = f2tf32(c[j][2]); hi.y = f2tf32(c[j][3]);
            *(uint2*)&g_Vt32[row * D + col]       = lo;
            *(uint2*)&g_Vt32[(row + 8) * D + col] = hi;
        }
    }
}

// ---------------------------------------------------------------------------
// k_main_mma v5 (verbatim from R14): MT=32, 512 threads, grid 313.
// ---------------------------------------------------------------------------
__global__ __launch_bounds__(512)
void k_main_mma(const float* __restrict__ dists,
                float* __restrict__ out,
                int N, int T, int step) {
    extern __shared__ __align__(16) uint32_t smem[];
    uint32_t* sv = smem;                       // [64][SVS]
    uint32_t* sd = smem + AA * SVS;            // [64][SDS]
    float*    sa = (float*)(smem + AA * SVS + AA * SDS);   // [MT][SAS]

    const int tid = threadIdx.x;
    const int w   = tid >> 5;
    const int l   = tid & 31;
    const int n0  = blockIdx.x * MT;

    // prefetch C rows for epilogue (warp w -> rows 2w, 2w+1)
    float4 cpre[2];
    int    nrow[2];
    #pragma unroll
    for (int r = 0; r < 2; r++) {
        const int n = n0 + 2 * w + r;
        nrow[r] = n;
        if (n < N) {
            const int t = (step * n) % T;
            cpre[r] = __ldg((const float4*)&g_C[(size_t)t * D + 4 * l]);
        }
    }

    // stage sd (DRAM; 1 uint4/thread)
    #pragma unroll
    for (int i = tid; i < AA * (MT / 4); i += 512) {
        const int a  = i / (MT / 4);
        const int j4 = (i % (MT / 4)) * 4;
        const int n  = n0 + j4;
        const float* src = dists + (size_t)a * N + n;
        float4 v;
        if (n + 3 < N) v = __ldg((const float4*)src);
        else {
            v.x = (n + 0 < N) ? src[0] : 0.f;
            v.y = (n + 1 < N) ? src[1] : 0.f;
            v.z = (n + 2 < N) ? src[2] : 0.f;
            v.w = (n + 3 < N) ? src[3] : 0.f;
        }
        uint4 t;
        t.x = f2tf32(v.x); t.y = f2tf32(v.y);
        t.z = f2tf32(v.z); t.w = f2tf32(v.w);
        *(uint4*)&sd[a * SDS + j4] = t;
    }

    // stage sv: pure copy of pre-converted tf32 bits
    #pragma unroll
    for (int i = tid; i < AA * (D / 4); i += 512) {
        const int a  = i >> 5;
        const int o4 = (i & 31) * 4;
        *(uint4*)&sv[a * SVS + o4] = __ldg((const uint4*)&g_Vt32[a * D + o4]);
    }
    __syncthreads();

    const int tig = l & 3;
    const int g   = l >> 2;
    const int mw  = w & 1;
    const int oq  = w >> 1;
    const int rowbase = 16 * mw;
    const int obase   = 16 * oq;

    float c[2][4];
    #pragma unroll
    for (int j = 0; j < 2; j++)
        #pragma unroll
        for (int q = 0; q < 4; q++) c[j][q] = 0.f;

    #pragma unroll
    for (int ks = 0; ks < 8; ks++) {
        const int k0 = 8 * ks + tig;
        const uint32_t a0 = sd[k0 * SDS + rowbase + g];
        const uint32_t a1 = sd[k0 * SDS + rowbase + g + 8];
        const uint32_t a2 = sd[(k0 + 4) * SDS + rowbase + g];
        const uint32_t a3 = sd[(k0 + 4) * SDS + rowbase + g + 8];
        #pragma unroll
        for (int j = 0; j < 2; j++) {
            const uint32_t b0 = sv[k0 * SVS + obase + 8 * j + g];
            const uint32_t b1 = sv[(k0 + 4) * SVS + obase + 8 * j + g];
            mma_tf32(c[j][0], c[j][1], c[j][2], c[j][3],
                     a0, a1, a2, a3, b0, b1);
        }
    }
    __syncthreads();

    #pragma unroll
    for (int j = 0; j < 2; j++) {
        const int col = obase + 8 * j + 2 * tig;
        float2 lo; lo.x = c[j][0]; lo.y = c[j][1];
        float2 hi; hi.x = c[j][2]; hi.y = c[j][3];
        *(float2*)&sa[(rowbase + g)     * SAS + col] = lo;
        *(float2*)&sa[(rowbase + g + 8) * SAS + col] = hi;
    }
    __syncthreads();

    #pragma unroll
    for (int r = 0; r < 2; r++) {
        const int n = nrow[r];
        if (n < N) {
            const float4 av = *(const float4*)&sa[(2 * w + r) * SAS + 4 * l];
            float4 o;
            o.x = av.x + cpre[r].x; o.y = av.y + cpre[r].y;
            o.z = av.z + cpre[r].z; o.w = av.w + cpre[r].w;
            *(float4*)&out[(size_t)n * D + 4 * l] = o;
        }
    }
}

// ---------------------------------------------------------------------------
extern "C" void kernel_launch(void* const* d_in, const int* in_sizes, int n_in,
                              void* d_out, int out_size) {
    const float* embeds = (const float*)d_in[0];   // [N, 128]
    const float* dists  = (const float*)d_in[1];   // [64, N]
    const float* W      = (const float*)d_in[2];   // [128, 256]
    const float* b      = (const float*)d_in[3];   // [128]
    const int*   anchor = (const int*)  d_in[4];   // [64] int32
    float* out = (float*)d_out;

    const int N = in_sizes[0] / D;                 // 10000

    int g = AA, y = N;                             // gcd(64, N) = 16
    while (y) { int r = g % y; g = y; y = r; }
    const int T    = N / g;                        // 625
    const int step = AA / g;                       // 4

    const int nCB    = (T + CT - 1) / CT;          // 20
    const int nTiles = (N + MT - 1) / MT;          // 313

    const int smemPre = PRE2_WORDS * 4;                        // 159520 B
    const int smemMMA = (AA * SVS + AA * SDS + MT * SAS) * 4;  // 61952 B

    cudaFuncSetAttribute(k_pre2, cudaFuncAttributeMaxDynamicSharedMemorySize, smemPre);
    cudaFuncSetAttribute(k_main_mma, cudaFuncAttributeMaxDynamicSharedMemorySize, smemMMA);

    k_pre2    <<<nCB + 1, 512, smemPre>>>(embeds, W, b, anchor, N, T, nCB);
    k_main_mma<<<nTiles, 512, smemMMA>>>(dists, out, N, T, step);
}

// round 16
// speedup vs baseline: 1.4068x; 1.4068x over previous
#include <cuda_runtime.h>
#include <cstdint>

#define D   128   // LATDIM
#define AA  64    // ANCHOR_SET_NUM
#define MT  32    // n rows per main tile -> grid 313
#define RW  8     // rows per k_pre tile -> 79 C + 8 V = 87 blocks
#define SDS 40    // sd stride (words); 40 % 32 == 8 -> conflict-free fragments
#define SVS 136   // sv stride (words); 136 % 32 == 8
#define SAS 132   // acc stride (words)

// __device__ scratch (allocation-free rule)
__device__ uint32_t g_Vt32[AA * D]; // V as tf32 bits [a][o]
__device__ float    g_C[10048 * D]; // [t][o]

// ---------------------------------------------------------------------------
// packed f32x2 helpers (k_pre)
// ---------------------------------------------------------------------------
__device__ __forceinline__ unsigned long long pk2(float x, float y) {
    unsigned long long r;
    asm("mov.b64 %0, {%1, %2};" : "=l"(r) : "f"(x), "f"(y));
    return r;
}
__device__ __forceinline__ void unpk2(unsigned long long v, float& x, float& y) {
    asm("mov.b64 {%0, %1}, %2;" : "=f"(x), "=f"(y) : "l"(v));
}
__device__ __forceinline__ void ffma2(unsigned long long& a,
                                      unsigned long long b, unsigned long long c) {
    asm("fma.rn.f32x2 %0, %1, %2, %0;" : "+l"(a) : "l"(b), "l"(c));
}
__device__ __forceinline__ void fadd2(unsigned long long& a, unsigned long long b) {
    asm("add.rn.f32x2 %0, %0, %1;" : "+l"(a) : "l"(b));
}

// ---------------------------------------------------------------------------
// tf32 helpers
// ---------------------------------------------------------------------------
__device__ __forceinline__ uint32_t f2tf32(float f) {
    uint32_t r;
    asm("cvt.rna.tf32.f32 %0, %1;" : "=r"(r) : "f"(f));
    return r;
}
__device__ __forceinline__ void mma_tf32(float& c0, float& c1, float& c2, float& c3,
                                         uint32_t a0, uint32_t a1, uint32_t a2,
                                         uint32_t a3, uint32_t b0, uint32_t b1) {
    asm("mma.sync.aligned.m16n8k8.row.col.f32.tf32.tf32.f32 "
        "{%0,%1,%2,%3}, {%4,%5,%6,%7}, {%8,%9}, {%0,%1,%2,%3};"
        : "+f"(c0), "+f"(c1), "+f"(c2), "+f"(c3)
        : "r"(a0), "r"(a1), "r"(a2), "r"(a3), "r"(b0), "r"(b1));
}

// ---------------------------------------------------------------------------
// k_pre (R13 verbatim; proven):
//   C[t][o] = (1/A) * sum_k E2[t][k] * W[o][D+k] + b[o]   (exact fp32)
//   V[a][o] = (1/A) * sum_k embeds[anchor[a]][k] * W[o][k] -> tf32 bits
// 87 blocks x 1024 threads.
// ---------------------------------------------------------------------------
__global__ __launch_bounds__(1024)
void k_pre(const float* __restrict__ embeds,
           const float* __restrict__ W,
           const float* __restrict__ b,
           const int*   __restrict__ anchor,
           int N, int T, int nC) {
    extern __shared__ __align__(16) float sm[];
    float (*Wc)[32][129] = (float(*)[32][129])sm;            // [4][32][129]
    float (*XT)[8]       = (float(*)[8])(sm + 4 * 32 * 129);
    float* sch           = sm + 4 * 32 * 129 + D * 8;        // [11][2][128]
    unsigned long long* spart = (unsigned long long*)sch;    // overlay after gemm

    const int tid  = threadIdx.x;
    const int w    = tid >> 5;
    const int l    = tid & 31;
    const bool isV = (blockIdx.x >= nC);
    const int  t0  = isV ? (blockIdx.x - nC) * RW : blockIdx.x * RW;
    const int  R   = isV ? RW : min(RW, T - t0);
    const int  woff = isV ? 0 : D;

    // stage all 4 W chunks (transposed, coalesced)
    {
        const int orow = tid >> 3;
        const int kq   = (tid & 7) * 4;
        #pragma unroll
        for (int kc = 0; kc < 4; kc++) {
            const float4 wv = __ldg((const float4*)
                &W[(size_t)orow * (2 * D) + woff + kc * 32 + kq]);
            Wc[kc][kq + 0][orow] = wv.x;
            Wc[kc][kq + 1][orow] = wv.y;
            Wc[kc][kq + 2][orow] = wv.z;
            Wc[kc][kq + 3][orow] = wv.w;
        }
    }

    // build XT[k][r]
    if (isV) {
        const int k = tid & 127, r = tid >> 7;
        XT[k][r] = __ldg(&embeds[(size_t)__ldg(&anchor[t0 + r]) * D + k]);
    } else {
        const int ch = w >> 1, half = w & 1;
        if (ch < R + 3) {
            const int rbase = 16 * (t0 + ch) + 8 * half;
            float4 acc = {0.f, 0.f, 0.f, 0.f};
            #pragma unroll
            for (int i = 0; i < 8; i++) {
                int r = rbase + i; if (r >= N) r -= N;
                const float4 v = __ldg((const float4*)&embeds[(size_t)r * D + 4 * l]);
                acc.x += v.x; acc.y += v.y; acc.z += v.z; acc.w += v.w;
            }
            *(float4*)&sch[(ch * 2 + half) * 128 + 4 * l] = acc;
        }
        __syncthreads();
        const int k = tid & 127, r = tid >> 7;
        float val = 0.f;
        if (r < R) {
            #pragma unroll
            for (int c = 0; c < 4; c++)
                val += sch[((r + c) * 2 + 0) * 128 + k]
                     + sch[((r + c) * 2 + 1) * 128 + k];
        }
        XT[k][r] = val;
    }
    __syncthreads();

    // gemm: thread (o, rq, h)
    const int o  = tid & 127;
    const int rq = (tid >> 7) & 1;
    const int h  = tid >> 8;
    unsigned long long a0 = 0ull, a1 = 0ull;

    #pragma unroll
    for (int kk = 0; kk < 32; kk++) {
        const float wv = Wc[h][kk][o];
        const ulonglong2 x = *(const ulonglong2*)&XT[h * 32 + kk][4 * rq];
        const unsigned long long ww = pk2(wv, wv);
        ffma2(a0, x.x, ww);
        ffma2(a1, x.y, ww);
    }
    __syncthreads();

    if (h > 0) {
        ulonglong2 t; t.x = a0; t.y = a1;
        *(ulonglong2*)&spart[(((h - 1) * 256) + o * 2 + rq) * 2] = t;
    }
    __syncthreads();

    if (h == 0) {
        #pragma unroll
        for (int hh = 0; hh < 3; hh++) {
            const ulonglong2 t =
                *(const ulonglong2*)&spart[((hh * 256) + o * 2 + rq) * 2];
            fadd2(a0, t.x); fadd2(a1, t.y);
        }
        float r0, r1, r2, r3;
        unpk2(a0, r0, r1); unpk2(a1, r2, r3);
        float res[4] = {r0, r1, r2, r3};
        const float sc = 1.0f / AA;
        if (isV) {
            #pragma unroll
            for (int i = 0; i < 4; i++)
                g_Vt32[(t0 + 4 * rq + i) * D + o] = f2tf32(res[i] * sc);
        } else {
            const float bias = __ldg(&b[o]);
            #pragma unroll
            for (int i = 0; i < 4; i++) {
                const int row = 4 * rq + i;
                if (row < R)
                    g_C[(size_t)(t0 + row) * D + o] = res[i] * sc + bias;
            }
        }
    }
}

// ---------------------------------------------------------------------------
// k_main_mma (R15/R14 verbatim; measured 8.3us): MT=32, 512 threads, grid 313.
// Warp = (mw 0..1 -> 16 n-rows, oq 0..7 -> 16 o-cols); 16 MMA/warp.
// C rows prefetched to registers; sv staging is a pure bit copy of g_Vt32.
// ---------------------------------------------------------------------------
__global__ __launch_bounds__(512)
void k_main_mma(const float* __restrict__ dists,
                float* __restrict__ out,
                int N, int T, int step) {
    extern __shared__ __align__(16) uint32_t smem[];
    uint32_t* sv = smem;                       // [64][SVS]
    uint32_t* sd = smem + AA * SVS;            // [64][SDS]
    float*    sa = (float*)(smem + AA * SVS + AA * SDS);   // [MT][SAS]

    const int tid = threadIdx.x;
    const int w   = tid >> 5;
    const int l   = tid & 31;
    const int n0  = blockIdx.x * MT;

    // prefetch C rows for epilogue (warp w -> rows 2w, 2w+1)
    float4 cpre[2];
    int    nrow[2];
    #pragma unroll
    for (int r = 0; r < 2; r++) {
        const int n = n0 + 2 * w + r;
        nrow[r] = n;
        if (n < N) {
            const int t = (step * n) % T;
            cpre[r] = __ldg((const float4*)&g_C[(size_t)t * D + 4 * l]);
        }
    }

    // stage sd (DRAM; 1 uint4/thread)
    #pragma unroll
    for (int i = tid; i < AA * (MT / 4); i += 512) {
        const int a  = i / (MT / 4);
        const int j4 = (i % (MT / 4)) * 4;
        const int n  = n0 + j4;
        const float* src = dists + (size_t)a * N + n;
        float4 v;
        if (n + 3 < N) v = __ldg((const float4*)src);
        else {
            v.x = (n + 0 < N) ? src[0] : 0.f;
            v.y = (n + 1 < N) ? src[1] : 0.f;
            v.z = (n + 2 < N) ? src[2] : 0.f;
            v.w = (n + 3 < N) ? src[3] : 0.f;
        }
        uint4 t;
        t.x = f2tf32(v.x); t.y = f2tf32(v.y);
        t.z = f2tf32(v.z); t.w = f2tf32(v.w);
        *(uint4*)&sd[a * SDS + j4] = t;
    }

    // stage sv: pure copy of pre-converted tf32 bits
    #pragma unroll
    for (int i = tid; i < AA * (D / 4); i += 512) {
        const int a  = i >> 5;
        const int o4 = (i & 31) * 4;
        *(uint4*)&sv[a * SVS + o4] = __ldg((const uint4*)&g_Vt32[a * D + o4]);
    }
    __syncthreads();

    const int tig = l & 3;
    const int g   = l >> 2;
    const int mw  = w & 1;          // m16 tile (2 per MT=32)
    const int oq  = w >> 1;         // o-eighth (16 cols)
    const int rowbase = 16 * mw;
    const int obase   = 16 * oq;

    float c[2][4];
    #pragma unroll
    for (int j = 0; j < 2; j++)
        #pragma unroll
        for (int q = 0; q < 4; q++) c[j][q] = 0.f;

    #pragma unroll
    for (int ks = 0; ks < 8; ks++) {
        const int k0 = 8 * ks + tig;
        const uint32_t a0 = sd[k0 * SDS + rowbase + g];
        const uint32_t a1 = sd[k0 * SDS + rowbase + g + 8];
        const uint32_t a2 = sd[(k0 + 4) * SDS + rowbase + g];
        const uint32_t a3 = sd[(k0 + 4) * SDS + rowbase + g + 8];
        #pragma unroll
        for (int j = 0; j < 2; j++) {
            const uint32_t b0 = sv[k0 * SVS + obase + 8 * j + g];
            const uint32_t b1 = sv[(k0 + 4) * SVS + obase + 8 * j + g];
            mma_tf32(c[j][0], c[j][1], c[j][2], c[j][3],
                     a0, a1, a2, a3, b0, b1);
        }
    }
    __syncthreads();

    #pragma unroll
    for (int j = 0; j < 2; j++) {
        const int col = obase + 8 * j + 2 * tig;
        float2 lo; lo.x = c[j][0]; lo.y = c[j][1];
        float2 hi; hi.x = c[j][2]; hi.y = c[j][3];
        *(float2*)&sa[(rowbase + g)     * SAS + col] = lo;
        *(float2*)&sa[(rowbase + g + 8) * SAS + col] = hi;
    }
    __syncthreads();

    #pragma unroll
    for (int r = 0; r < 2; r++) {
        const int n = nrow[r];
        if (n < N) {
            const float4 av = *(const float4*)&sa[(2 * w + r) * SAS + 4 * l];
            float4 o;
            o.x = av.x + cpre[r].x; o.y = av.y + cpre[r].y;
            o.z = av.z + cpre[r].z; o.w = av.w + cpre[r].w;
            *(float4*)&out[(size_t)n * D + 4 * l] = o;
        }
    }
}

// ---------------------------------------------------------------------------
extern "C" void kernel_launch(void* const* d_in, const int* in_sizes, int n_in,
                              void* d_out, int out_size) {
    const float* embeds = (const float*)d_in[0];   // [N, 128]
    const float* dists  = (const float*)d_in[1];   // [64, N]
    const float* W      = (const float*)d_in[2];   // [128, 256]
    const float* b      = (const float*)d_in[3];   // [128]
    const int*   anchor = (const int*)  d_in[4];   // [64] int32
    float* out = (float*)d_out;

    const int N = in_sizes[0] / D;                 // 10000

    int g = AA, y = N;                             // gcd(64, N) = 16
    while (y) { int r = g % y; g = y; y = r; }
    const int T    = N / g;                        // 625
    const int step = AA / g;                       // 4

    const int nC     = (T + RW - 1) / RW;          // 79
    const int nTiles = (N + MT - 1) / MT;          // 313
    const int smemPre = (4 * 32 * 129 + D * 8) * 4 + 12288;       // 82432 B
    const int smemMMA = (AA * SVS + AA * SDS + MT * SAS) * 4;     // 61952 B

    cudaFuncSetAttribute(k_pre, cudaFuncAttributeMaxDynamicSharedMemorySize, smemPre);
    cudaFuncSetAttribute(k_main_mma, cudaFuncAttributeMaxDynamicSharedMemorySize, smemMMA);

    k_pre     <<<nC + AA / RW, 1024, smemPre>>>(embeds, W, b, anchor, N, T, nC);
    k_main_mma<<<nTiles, 512, smemMMA>>>(dists, out, N, T, step);
}